// round 1
// baseline (speedup 1.0000x reference)
#include <cuda_runtime.h>

#define NTOK 512
#define DSTATE 192
#define HID 512
#define EMB 1024
#define NEMB 32
#define KC 256
#define HS_STRIDE 34

// scratch (allocs forbidden -> device globals)
__device__ int g_start[NEMB + 1];
__device__ int g_tokens[NTOK];
__device__ float g_H[NTOK * 4 * HID]; // [slot][m][HID], grouped slot order

struct Params {
    const float* W1[4];
    const float* b1[4];
    const float* W2[4];
    const float* b2[4];
    const float* te[4];
};

// ---------------------------------------------------------------------------
// Kernel 0: group tokens by embodiment id. Handles int32 OR int64 id buffers.
// ---------------------------------------------------------------------------
__global__ void k_group(const int* __restrict__ ids_raw) {
    __shared__ int s_cnt[NEMB];
    __shared__ int s_pos[NEMB];
    __shared__ int s_i64;
    int tid = threadIdx.x; // 512 threads

    if (tid < NEMB) s_cnt[tid] = 0;
    if (tid == 0) s_i64 = 1;
    __syncthreads();

    // int64 ids (<32) have zero high words at all odd int32 indices.
    // int32 ids would put 256 random ids at odd indices -> ~surely nonzero.
    if (tid < 256) {
        if (ids_raw[2 * tid + 1] != 0) s_i64 = 0;
    }
    __syncthreads();

    int c = s_i64 ? ids_raw[2 * tid] : ids_raw[tid];
    atomicAdd(&s_cnt[c], 1);
    __syncthreads();

    if (tid <= NEMB) {
        int s = 0;
        for (int j = 0; j < tid && j < NEMB; j++) s += s_cnt[j];
        g_start[tid] = s;
        if (tid < NEMB) s_pos[tid] = s;
    }
    __syncthreads();

    int slot = atomicAdd(&s_pos[c], 1);
    g_tokens[slot] = tid;
}

// ---------------------------------------------------------------------------
// Kernel 1: H[slot][m][:] = relu(x_m . W1_m[e] + b1_m[e]) for grouped tokens.
// Grid: 128 blocks = (e,m). 512 threads = one HID column each.
// ---------------------------------------------------------------------------
__global__ void __launch_bounds__(512) k_stage1(const float* __restrict__ state, Params p) {
    const int Ls[4]   = {64, 64, 32, 32};
    const int offs[4] = {0, 64, 128, 160};
    int m = blockIdx.x & 3;
    int e = blockIdx.x >> 2;
    int L = Ls[m], off = offs[m];
    int s0 = g_start[e];
    int n  = g_start[e + 1] - s0;
    if (n == 0) return;

    int j = threadIdx.x;
    const float* __restrict__ W1 = p.W1[m] + (size_t)e * L * HID;
    float b = p.b1[m][e * HID + j];

    __shared__ float xs[16 * 64];

    for (int cb = 0; cb < n; cb += 16) {
        int rem = min(n - cb, 16);
        __syncthreads();
        for (int idx = j; idx < 16 * 64; idx += 512) {
            int tk = idx >> 6, l = idx & 63;
            float v = 0.f;
            if (tk < rem && l < L) {
                int tok = g_tokens[s0 + cb + tk];
                v = state[tok * DSTATE + off + l];
            }
            xs[idx] = v;
        }
        __syncthreads();

        float acc[16];
        #pragma unroll
        for (int t = 0; t < 16; t++) acc[t] = b;

        for (int l = 0; l < L; l++) {
            float w = W1[l * HID + j];
            #pragma unroll
            for (int t = 0; t < 16; t++)
                acc[t] = fmaf(xs[t * 64 + l], w, acc[t]);
        }

        #pragma unroll
        for (int t = 0; t < 16; t++) {
            if (t < rem)
                g_H[((size_t)(s0 + cb + t) * 4 + m) * HID + j] = fmaxf(acc[t], 0.f);
        }
    }
}

// ---------------------------------------------------------------------------
// Kernel 2: out = H . W2[e] + b2[e] + te. One block = (col tile of 128, m, e).
// Streams W2 slice once; tokens packed as f32x2 pairs in registers.
// ---------------------------------------------------------------------------
template <int P>
__device__ __forceinline__ void run_chunk(
    float* hs, const float* __restrict__ W2ec, const float* __restrict__ Hme,
    float init, int s0cb, int rem, int tid, int m, int c, float* __restrict__ out)
{
    unsigned long long acc[P];
    unsigned long long ivl;
    asm("mov.b64 %0, {%1, %1};" : "=l"(ivl) : "r"(__float_as_uint(init)));
    #pragma unroll
    for (int p = 0; p < P; p++) acc[p] = ivl;

    for (int kc = 0; kc < HID; kc += KC) {
        __syncthreads();
        // stage h transposed: hs[kk*HS_STRIDE + tk], tk in [0, 2P)
        #pragma unroll
        for (int tk = 0; tk < 2 * P; tk++) {
            int slot = min(s0cb + tk, NTOK - 1); // pad slot clamp (discarded later)
            const float* src = Hme + (size_t)slot * (4 * HID) + kc;
            for (int kk = tid; kk < KC; kk += 128)
                hs[kk * HS_STRIDE + tk] = src[kk];
        }
        __syncthreads();

        const float* wp = W2ec + (size_t)kc * EMB;
        #pragma unroll 4
        for (int kk = 0; kk < KC; kk++) {
            float w = __ldcs(wp + kk * EMB);
            unsigned long long w2;
            asm("mov.b64 %0, {%1, %1};" : "=l"(w2) : "r"(__float_as_uint(w)));
            const float* hrow = hs + kk * HS_STRIDE;
            #pragma unroll
            for (int p = 0; p < P; p++) {
                unsigned long long h2 = *(const unsigned long long*)(hrow + 2 * p);
                asm("fma.rn.f32x2 %0, %1, %2, %0;" : "+l"(acc[p]) : "l"(h2), "l"(w2));
            }
        }
    }

    #pragma unroll
    for (int p = 0; p < P; p++) {
        float2 v = *(float2*)&acc[p];
        int i0 = 2 * p;
        if (i0 < rem) {
            int tok = g_tokens[s0cb + i0];
            out[((size_t)tok * 4 + m) * EMB + c] = v.x;
        }
        if (i0 + 1 < rem) {
            int tok = g_tokens[s0cb + i0 + 1];
            out[((size_t)tok * 4 + m) * EMB + c] = v.y;
        }
    }
}

__global__ void __launch_bounds__(128) k_stage2(Params p, float* __restrict__ out) {
    int tile = blockIdx.x; // 0..7
    int m    = blockIdx.y; // 0..3
    int e    = blockIdx.z; // 0..31
    int s0 = g_start[e];
    int n  = g_start[e + 1] - s0;
    if (n == 0) return;

    int tid = threadIdx.x;
    int c = tile * 128 + tid;
    const float* __restrict__ W2ec = p.W2[m] + (size_t)e * HID * EMB + c;
    const float* __restrict__ Hme  = g_H + m * HID;
    float init = p.b2[m][e * EMB + c] + p.te[m][c];

    __shared__ __align__(16) float hs[KC * HS_STRIDE];

    for (int cb = 0; cb < n; cb += 32) {
        int rem = min(n - cb, 32);
        int pairs = (rem + 1) >> 1;
        int s0cb = s0 + cb;
        switch (pairs) {
#define CASE(PP) case PP: run_chunk<PP>(hs, W2ec, Hme, init, s0cb, rem, tid, m, c, out); break;
            CASE(1) CASE(2) CASE(3) CASE(4) CASE(5) CASE(6) CASE(7) CASE(8)
            CASE(9) CASE(10) CASE(11) CASE(12) CASE(13) CASE(14) CASE(15) CASE(16)
#undef CASE
        }
    }
}

// ---------------------------------------------------------------------------
extern "C" void kernel_launch(void* const* d_in, const int* in_sizes, int n_in,
                              void* d_out, int out_size) {
    const float* state = (const float*)d_in[0];
    const int*   ids   = (const int*)d_in[1];

    Params P;
    int base = 2;
    for (int m = 0; m < 4; m++) {
        P.W1[m] = (const float*)d_in[base + 0];
        P.b1[m] = (const float*)d_in[base + 1];
        P.W2[m] = (const float*)d_in[base + 2];
        P.b2[m] = (const float*)d_in[base + 3];
        P.te[m] = (const float*)d_in[base + 4];
        base += 5;
    }
    float* out = (float*)d_out;

    k_group<<<1, 512>>>(ids);
    k_stage1<<<128, 512>>>(state, P);
    k_stage2<<<dim3(8, 4, 32), 128>>>(P, out);
}